// round 1
// baseline (speedup 1.0000x reference)
#include <cuda_runtime.h>

#define ROWS 1024
#define COLS 1024
#define NN (ROWS * COLS)

#define RHOGW 9810.0f            // RHO_W * GRAV
#define INV_SEC_PER_A (1.0f / 31556926.0f)
#define FLOW_COEFF 0.0405f

// Scratch (device globals: no allocations allowed)
__device__ float  g_phi[NN];
__device__ float  g_gs[NN];      // core / s_safe  (0 on boundary)
__device__ float4 g_w4[NN];      // incoming weights: {from left, right, up, down}
__device__ float  g_runoff[NN];
__device__ float  g_q[2][NN];

__global__ __launch_bounds__(256) void k_setup(const float* __restrict__ melt,
                                               const float* __restrict__ bed,
                                               const float* __restrict__ wp,
                                               const float* __restrict__ area) {
    int i = blockIdx.x * blockDim.x + threadIdx.x;
    if (i >= NN) return;
    g_phi[i] = RHOGW * bed[i] + wp[i];
    float r = melt[i] * area[i] * INV_SEC_PER_A;
    g_runoff[i] = r;
    g_q[0][i] = r;
}

__global__ __launch_bounds__(256) void k_gs(const int* __restrict__ status) {
    int i = blockIdx.x * blockDim.x + threadIdx.x;
    if (i >= NN) return;
    int c = i & (COLS - 1);
    int r = i >> 10;
    float p = g_phi[i];
    float s = 0.0f;
    if (c > 0)        s += fmaxf(p - g_phi[i - 1], 0.0f);
    if (c < COLS - 1) s += fmaxf(p - g_phi[i + 1], 0.0f);
    if (r > 0)        s += fmaxf(p - g_phi[i - COLS], 0.0f);
    if (r < ROWS - 1) s += fmaxf(p - g_phi[i + COLS], 0.0f);
    float gs = 0.0f;
    if (status[i] == 0) gs = (s > 0.0f) ? (1.0f / s) : 1.0f;
    g_gs[i] = gs;
}

__global__ __launch_bounds__(256) void k_w(void) {
    int i = blockIdx.x * blockDim.x + threadIdx.x;
    if (i >= NN) return;
    int c = i & (COLS - 1);
    int r = i >> 10;
    float p = g_phi[i];
    float4 w = make_float4(0.0f, 0.0f, 0.0f, 0.0f);
    if (c > 0)        w.x = fmaxf(g_phi[i - 1] - p, 0.0f) * g_gs[i - 1];
    if (c < COLS - 1) w.y = fmaxf(g_phi[i + 1] - p, 0.0f) * g_gs[i + 1];
    if (r > 0)        w.z = fmaxf(g_phi[i - COLS] - p, 0.0f) * g_gs[i - COLS];
    if (r < ROWS - 1) w.w = fmaxf(g_phi[i + COLS] - p, 0.0f) * g_gs[i + COLS];
    g_w4[i] = w;
}

template <bool FINAL>
__global__ __launch_bounds__(256) void k_iter(int src,
                                              const float* __restrict__ conduit,
                                              float* __restrict__ out) {
    int i = blockIdx.x * blockDim.x + threadIdx.x;
    if (i >= NN) return;
    int c = i & (COLS - 1);
    int r = i >> 10;
    const float* __restrict__ q = g_q[src];
    float4 w = g_w4[i];
    float acc = g_runoff[i];
    if (c > 0)        acc += w.x * q[i - 1];
    if (c < COLS - 1) acc += w.y * q[i + 1];
    if (r > 0)        acc += w.z * q[i - COLS];
    if (r < ROWS - 1) acc += w.w * q[i + COLS];
    if (FINAL) {
        float cd = conduit[i];
        float c125 = cd * sqrtf(sqrtf(cd));      // conduit^1.25
        float t = acc * FLOW_COEFF * c125;
        out[i] = (g_gs[i] != 0.0f) ? (t * t) : 0.0f;
    } else {
        g_q[src ^ 1][i] = acc;
    }
}

extern "C" void kernel_launch(void* const* d_in, const int* in_sizes, int n_in,
                              void* d_out, int out_size) {
    const float* melt    = (const float*)d_in[0];
    const float* bed     = (const float*)d_in[1];
    const float* wp      = (const float*)d_in[2];
    const float* area    = (const float*)d_in[3];
    const float* conduit = (const float*)d_in[4];
    const int*   status  = (const int*)d_in[5];
    float* out = (float*)d_out;

    const int T = 256;
    const int B = NN / T;

    k_setup<<<B, T>>>(melt, bed, wp, area);
    k_gs<<<B, T>>>(status);
    k_w<<<B, T>>>();

    // 32 fixed-point sweeps; last one fuses the gradient epilogue.
    int src = 0;
    for (int t = 0; t < 31; ++t) {
        k_iter<false><<<B, T>>>(src, conduit, out);
        src ^= 1;
    }
    k_iter<true><<<B, T>>>(src, conduit, out);
}

// round 2
// speedup vs baseline: 2.3211x; 2.3211x over previous
#include <cuda_runtime.h>

#define ROWS 1024
#define COLS 1024
#define NN (ROWS * COLS)

#define RHOGW 9810.0f            // RHO_W * GRAV
#define INV_SEC_PER_A (1.0f / 31556926.0f)
#define FLOW_COEFF 0.0405f

#define TS 32                    // output tile
#define KF 8                     // fused iterations per launch
#define RW (TS + 2*KF)           // 48: region width
#define RN (RW * RW)             // 2304
#define SPAD RW                  // smem guard pad (one row each side)

// Scratch (device globals: no allocations allowed)
__device__ float  g_phi[NN];
__device__ float  g_gs[NN];      // core / s_safe (0 on boundary)
__device__ float4 g_w4[NN];      // incoming weights: {from left, right, up, down}
__device__ float  g_runoff[NN];
__device__ float  g_q[2][NN];

__global__ __launch_bounds__(256) void k_setup(const float* __restrict__ melt,
                                               const float* __restrict__ bed,
                                               const float* __restrict__ wp,
                                               const float* __restrict__ area) {
    int i = blockIdx.x * blockDim.x + threadIdx.x;
    if (i >= NN) return;
    g_phi[i] = RHOGW * bed[i] + wp[i];
    g_runoff[i] = melt[i] * area[i] * INV_SEC_PER_A;
}

__global__ __launch_bounds__(256) void k_gs(const int* __restrict__ status) {
    int i = blockIdx.x * blockDim.x + threadIdx.x;
    if (i >= NN) return;
    int c = i & (COLS - 1);
    int r = i >> 10;
    float p = g_phi[i];
    float s = 0.0f;
    if (c > 0)        s += fmaxf(p - g_phi[i - 1], 0.0f);
    if (c < COLS - 1) s += fmaxf(p - g_phi[i + 1], 0.0f);
    if (r > 0)        s += fmaxf(p - g_phi[i - COLS], 0.0f);
    if (r < ROWS - 1) s += fmaxf(p - g_phi[i + COLS], 0.0f);
    float gs = 0.0f;
    if (status[i] == 0) gs = (s > 0.0f) ? (1.0f / s) : 1.0f;
    g_gs[i] = gs;
}

__global__ __launch_bounds__(256) void k_w(void) {
    int i = blockIdx.x * blockDim.x + threadIdx.x;
    if (i >= NN) return;
    int c = i & (COLS - 1);
    int r = i >> 10;
    float p = g_phi[i];
    float4 w = make_float4(0.0f, 0.0f, 0.0f, 0.0f);
    if (c > 0)        w.x = fmaxf(g_phi[i - 1] - p, 0.0f) * g_gs[i - 1];
    if (c < COLS - 1) w.y = fmaxf(g_phi[i + 1] - p, 0.0f) * g_gs[i + 1];
    if (r > 0)        w.z = fmaxf(g_phi[i - COLS] - p, 0.0f) * g_gs[i - COLS];
    if (r < ROWS - 1) w.w = fmaxf(g_phi[i + COLS] - p, 0.0f) * g_gs[i + COLS];
    g_w4[i] = w;
}

// Fused KF Jacobi iterations on a 48x48 region producing a 32x32 central tile.
// 256 threads, each owns a 3x3 patch. Weights + runoff in registers; q ping-pongs
// in shared memory. Halo contamination moves 1 node/iter -> central tile exact.
template <bool INIT, bool FINAL>
__global__ __launch_bounds__(256, 2)
void k_fused(int qsel,
             const float* __restrict__ conduit,
             const int*  __restrict__ status,
             float* __restrict__ out) {
    __shared__ float sq[2][RN + 2 * SPAD];

    const int tid = threadIdx.x;
    const int tx = tid & 15, ty = tid >> 4;
    const int px = tx * 3, py = ty * 3;
    const int ox = blockIdx.x * TS - KF;
    const int oy = blockIdx.y * TS - KF;

    const float* __restrict__ qsrc = g_q[qsel];
    float*       __restrict__ qdst = g_q[qsel ^ 1];

    // zero guard pads (never written afterwards)
    if (tid < SPAD) {
        sq[0][tid] = 0.0f;
        sq[1][tid] = 0.0f;
        sq[0][SPAD + RN + tid] = 0.0f;
        sq[1][SPAD + RN + tid] = 0.0f;
    }

    float4 w[9];
    float  ro[9];
#pragma unroll
    for (int j = 0; j < 9; j++) {
        const int ly = py + j / 3, lx = px + j % 3;
        const int gy = oy + ly, gx = ox + lx;
        const bool ok = (gx >= 0) & (gx < COLS) & (gy >= 0) & (gy < ROWS);
        const int g = gy * COLS + gx;
        float4 wv = make_float4(0.0f, 0.0f, 0.0f, 0.0f);
        float  r = 0.0f, q0 = 0.0f;
        if (ok) {
            wv = g_w4[g];
            r  = g_runoff[g];
            q0 = INIT ? r : qsrc[g];
        }
        w[j] = wv;
        ro[j] = r;
        sq[0][SPAD + ly * RW + lx] = q0;
    }
    __syncthreads();

    int cur = 0;
    const int base = py * RW + px;
    for (int it = 0; it < KF; it++) {
        const float* __restrict__ qs = &sq[cur][SPAD];
        float* __restrict__       qd = &sq[cur ^ 1][SPAD];

        float u[3], m[3][5], d[3];
#pragma unroll
        for (int c = 0; c < 3; c++) u[c] = qs[base - RW + c];
#pragma unroll
        for (int r = 0; r < 3; r++)
#pragma unroll
            for (int c = 0; c < 5; c++) m[r][c] = qs[base + r * RW + c - 1];
#pragma unroll
        for (int c = 0; c < 3; c++) d[c] = qs[base + 3 * RW + c];

        float n[3][3];
#pragma unroll
        for (int r = 0; r < 3; r++) {
#pragma unroll
            for (int c = 0; c < 3; c++) {
                const int j = r * 3 + c;
                const float up = (r == 0) ? u[c] : m[r - 1][c + 1];
                const float dn = (r == 2) ? d[c] : m[r + 1][c + 1];
                float acc = ro[j];
                acc = fmaf(w[j].x, m[r][c],     acc);
                acc = fmaf(w[j].y, m[r][c + 2], acc);
                acc = fmaf(w[j].z, up,          acc);
                acc = fmaf(w[j].w, dn,          acc);
                n[r][c] = acc;
            }
        }
#pragma unroll
        for (int r = 0; r < 3; r++)
#pragma unroll
            for (int c = 0; c < 3; c++) qd[base + r * RW + c] = n[r][c];
        __syncthreads();
        cur ^= 1;
    }

    // cur == 0 after KF=8 iterations
    const float* __restrict__ qf = &sq[cur][SPAD];
#pragma unroll
    for (int j = 0; j < 9; j++) {
        const int ly = py + j / 3, lx = px + j % 3;
        if (lx >= KF && lx < KF + TS && ly >= KF && ly < KF + TS) {
            const int gy = oy + ly, gx = ox + lx;
            const int g = gy * COLS + gx;
            const float q = qf[ly * RW + lx];
            if (FINAL) {
                const float cd = conduit[g];
                const float c125 = cd * sqrtf(sqrtf(cd));   // conduit^1.25
                const float t = q * FLOW_COEFF * c125;
                out[g] = (status[g] == 0) ? (t * t) : 0.0f;
            } else {
                qdst[g] = q;
            }
        }
    }
}

extern "C" void kernel_launch(void* const* d_in, const int* in_sizes, int n_in,
                              void* d_out, int out_size) {
    const float* melt    = (const float*)d_in[0];
    const float* bed     = (const float*)d_in[1];
    const float* wp      = (const float*)d_in[2];
    const float* area    = (const float*)d_in[3];
    const float* conduit = (const float*)d_in[4];
    const int*   status  = (const int*)d_in[5];
    float* out = (float*)d_out;

    const int T = 256;
    const int B = NN / T;

    k_setup<<<B, T>>>(melt, bed, wp, area);
    k_gs<<<B, T>>>(status);
    k_w<<<B, T>>>();

    dim3 grid(COLS / TS, ROWS / TS);   // 32 x 32 tiles
    // 4 launches x 8 fused iterations = 32 iterations total
    k_fused<true,  false><<<grid, T>>>(0, conduit, status, out);  // runoff -> g_q[1]
    k_fused<false, false><<<grid, T>>>(1, conduit, status, out);  // g_q[1] -> g_q[0]
    k_fused<false, false><<<grid, T>>>(0, conduit, status, out);  // g_q[0] -> g_q[1]
    k_fused<false, true ><<<grid, T>>>(1, conduit, status, out);  // g_q[1] -> out
}

// round 3
// speedup vs baseline: 3.0720x; 1.3235x over previous
#include <cuda_runtime.h>

#define ROWS 1024
#define COLS 1024
#define NN (ROWS * COLS)

#define RHOGW 9810.0f            // RHO_W * GRAV
#define INV_SEC_PER_A (1.0f / 31556926.0f)
#define FLOW_COEFF 0.0405f

#define TS 32                    // output tile
#define KF 8                     // fused iterations per launch
#define RW (TS + 2*KF)           // 48
#define RN (RW * RW)             // 2304
#define SPAD RW                  // smem guard pad (one row each side)

// Scratch (device globals: no allocations allowed)
__device__ float4 g_w4[NN];      // incoming weights: {left, right, up, down}
__device__ float  g_runoff[NN];
__device__ float  g_q[2][NN];

// ---------------- fused prep: phi -> gs -> w4 + runoff, one pass ----------------
#define PT 32
#define PH2 36                   // phi tile (halo 2)
#define PH1 34                   // gs tile (halo 1)

__global__ __launch_bounds__(256) void k_prep(const float* __restrict__ melt,
                                              const float* __restrict__ bed,
                                              const float* __restrict__ wp,
                                              const float* __restrict__ area,
                                              const int*  __restrict__ status) {
    __shared__ float sphi[PH2 * PH2];
    __shared__ float sgs[PH1 * PH1];
    const int ox = blockIdx.x * PT, oy = blockIdx.y * PT;

    for (int idx = threadIdx.x; idx < PH2 * PH2; idx += 256) {
        int iy = idx / PH2, ix = idx % PH2;
        int gy = oy + iy - 2, gx = ox + ix - 2;
        float p = __int_as_float(0x7f800000);     // +INF sentinel: contributes 0 drop
        if (gx >= 0 && gx < COLS && gy >= 0 && gy < ROWS) {
            int g = gy * COLS + gx;
            p = fmaf(RHOGW, bed[g], wp[g]);
        }
        sphi[idx] = p;
    }
    __syncthreads();

    for (int idx = threadIdx.x; idx < PH1 * PH1; idx += 256) {
        int iy = idx / PH1, ix = idx % PH1;
        int gy = oy + iy - 1, gx = ox + ix - 1;
        float gs = 0.0f;
        if (gx >= 0 && gx < COLS && gy >= 0 && gy < ROWS) {
            int g = gy * COLS + gx;
            if (status[g] == 0) {
                int c = (iy + 1) * PH2 + (ix + 1);
                float p = sphi[c];
                float s = 0.0f;
                s += fmaxf(p - sphi[c - 1], 0.0f);
                s += fmaxf(p - sphi[c + 1], 0.0f);
                s += fmaxf(p - sphi[c - PH2], 0.0f);
                s += fmaxf(p - sphi[c + PH2], 0.0f);
                gs = (s > 0.0f) ? (1.0f / s) : 1.0f;
            }
        }
        sgs[idx] = gs;
    }
    __syncthreads();

    for (int idx = threadIdx.x; idx < PT * PT; idx += 256) {
        int iy = idx / PT, ix = idx % PT;
        int gy = oy + iy, gx = ox + ix;
        int g = gy * COLS + gx;
        int cp = (iy + 2) * PH2 + (ix + 2);
        int cg = (iy + 1) * PH1 + (ix + 1);
        float p = sphi[cp];
        float4 w = make_float4(0.0f, 0.0f, 0.0f, 0.0f);
        if (gx > 0)        w.x = fmaxf(sphi[cp - 1]   - p, 0.0f) * sgs[cg - 1];
        if (gx < COLS - 1) w.y = fmaxf(sphi[cp + 1]   - p, 0.0f) * sgs[cg + 1];
        if (gy > 0)        w.z = fmaxf(sphi[cp - PH2] - p, 0.0f) * sgs[cg - PH1];
        if (gy < ROWS - 1) w.w = fmaxf(sphi[cp + PH2] - p, 0.0f) * sgs[cg + PH1];
        g_w4[g] = w;
        g_runoff[g] = melt[g] * area[g] * INV_SEC_PER_A;
    }
}

// ---------------- fused Jacobi: 8 iters, patch in registers, ring via smem ----------------
// 256 threads, each owns a 3x3 patch of a 48x48 region (32x32 tile + halo 8).
// Interior neighbor values live in registers; only the 12-ring is read from smem
// and only the 8 border cells are written per iteration.
template <bool INIT, bool FINAL>
__global__ __launch_bounds__(256, 3)
void k_fused(int qsel,
             const float* __restrict__ conduit,
             const int*  __restrict__ status,
             float* __restrict__ out) {
    __shared__ float sq[2][RN + 2 * SPAD];

    const int tid = threadIdx.x;
    const int tx = tid & 15, ty = tid >> 4;
    const int px = tx * 3, py = ty * 3;
    const int ox = blockIdx.x * TS - KF;
    const int oy = blockIdx.y * TS - KF;

    const float* __restrict__ qsrc = g_q[qsel];
    float*       __restrict__ qdst = g_q[qsel ^ 1];

    // zero guard pads (one row above/below region, never written afterwards)
    if (tid < SPAD) {
        sq[0][tid] = 0.0f;
        sq[1][tid] = 0.0f;
        sq[0][SPAD + RN + tid] = 0.0f;
        sq[1][SPAD + RN + tid] = 0.0f;
    }

    const int base = SPAD + py * RW + px;

    float4 w[3][3];
    float  ro[3][3];
    float  q[3][3];
#pragma unroll
    for (int r = 0; r < 3; r++) {
#pragma unroll
        for (int c = 0; c < 3; c++) {
            const int gy = oy + py + r, gx = ox + px + c;
            const bool ok = (gx >= 0) & (gx < COLS) & (gy >= 0) & (gy < ROWS);
            const int g = gy * COLS + gx;
            float4 wv = make_float4(0.0f, 0.0f, 0.0f, 0.0f);
            float rv = 0.0f, qv = 0.0f;
            if (ok) {
                wv = g_w4[g];
                rv = g_runoff[g];
                qv = INIT ? rv : qsrc[g];
            }
            w[r][c] = wv; ro[r][c] = rv; q[r][c] = qv;
            if (!(r == 1 && c == 1)) sq[0][base + r * RW + c] = qv;  // seed borders
        }
    }
    __syncthreads();

#pragma unroll
    for (int it = 0; it < KF; it++) {
        const int cur = it & 1;
        const float* __restrict__ qs = sq[cur];
        float*       __restrict__ qd = sq[cur ^ 1];

        // 12-ring from neighboring threads (previous iteration values)
        float t0 = qs[base - RW],     t1 = qs[base - RW + 1],     t2 = qs[base - RW + 2];
        float b0 = qs[base + 3 * RW], b1 = qs[base + 3 * RW + 1], b2 = qs[base + 3 * RW + 2];
        float l0 = qs[base - 1],      l1 = qs[base + RW - 1],     l2 = qs[base + 2 * RW - 1];
        float r0 = qs[base + 3],      r1 = qs[base + RW + 3],     r2 = qs[base + 2 * RW + 3];

        float n[3][3];
#pragma unroll
        for (int r = 0; r < 3; r++) {
#pragma unroll
            for (int c = 0; c < 3; c++) {
                const float lf = (c == 0) ? ((r == 0) ? l0 : (r == 1) ? l1 : l2) : q[r][c - 1];
                const float rt = (c == 2) ? ((r == 0) ? r0 : (r == 1) ? r1 : r2) : q[r][c + 1];
                const float up = (r == 0) ? ((c == 0) ? t0 : (c == 1) ? t1 : t2) : q[r - 1][c];
                const float dn = (r == 2) ? ((c == 0) ? b0 : (c == 1) ? b1 : b2) : q[r + 1][c];
                float acc = ro[r][c];
                acc = fmaf(w[r][c].x, lf, acc);
                acc = fmaf(w[r][c].y, rt, acc);
                acc = fmaf(w[r][c].z, up, acc);
                acc = fmaf(w[r][c].w, dn, acc);
                n[r][c] = acc;
            }
        }
        // publish only the 8 border cells of the patch
        qd[base]              = n[0][0];
        qd[base + 1]          = n[0][1];
        qd[base + 2]          = n[0][2];
        qd[base + RW]         = n[1][0];
        qd[base + RW + 2]     = n[1][2];
        qd[base + 2 * RW]     = n[2][0];
        qd[base + 2 * RW + 1] = n[2][1];
        qd[base + 2 * RW + 2] = n[2][2];
        __syncthreads();
#pragma unroll
        for (int r = 0; r < 3; r++)
#pragma unroll
            for (int c = 0; c < 3; c++) q[r][c] = n[r][c];
    }

    // write central 32x32 from registers
#pragma unroll
    for (int r = 0; r < 3; r++) {
#pragma unroll
        for (int c = 0; c < 3; c++) {
            const int ly = py + r, lx = px + c;
            if (lx >= KF && lx < KF + TS && ly >= KF && ly < KF + TS) {
                const int g = (oy + ly) * COLS + (ox + lx);
                if (FINAL) {
                    const float cd = conduit[g];
                    const float c125 = cd * sqrtf(sqrtf(cd));   // conduit^1.25
                    const float t = q[r][c] * FLOW_COEFF * c125;
                    out[g] = (status[g] == 0) ? (t * t) : 0.0f;
                } else {
                    qdst[g] = q[r][c];
                }
            }
        }
    }
}

extern "C" void kernel_launch(void* const* d_in, const int* in_sizes, int n_in,
                              void* d_out, int out_size) {
    const float* melt    = (const float*)d_in[0];
    const float* bed     = (const float*)d_in[1];
    const float* wp      = (const float*)d_in[2];
    const float* area    = (const float*)d_in[3];
    const float* conduit = (const float*)d_in[4];
    const int*   status  = (const int*)d_in[5];
    float* out = (float*)d_out;

    dim3 pgrid(COLS / PT, ROWS / PT);
    k_prep<<<pgrid, 256>>>(melt, bed, wp, area, status);

    dim3 grid(COLS / TS, ROWS / TS);   // 32 x 32 tiles
    // 4 launches x 8 fused iterations = 32 iterations total
    k_fused<true,  false><<<grid, 256>>>(0, conduit, status, out);  // runoff -> g_q[1]
    k_fused<false, false><<<grid, 256>>>(1, conduit, status, out);  // g_q[1] -> g_q[0]
    k_fused<false, false><<<grid, 256>>>(0, conduit, status, out);  // g_q[0] -> g_q[1]
    k_fused<false, true ><<<grid, 256>>>(1, conduit, status, out);  // g_q[1] -> out
}